// round 10
// baseline (speedup 1.0000x reference)
#include <cuda_runtime.h>

// Problem constants (from reference)
#define NB_B     2
#define NB_NGT   64
#define NB_G     6
#define NB_C     64
#define NB_NVOX  100000
#define NB_NTOT  (NB_B * NB_NVOX)      // 200000 voxels per branch
#define NB_DZ    10
#define NB_DY    400
#define NB_DX    352
#define CELLS    (NB_B * NB_DZ * NB_DY * NB_DX)   // 2,816,000
#define NROI     (NB_B * NB_NGT)                   // 128
#define G3       (NB_G * NB_G * NB_G)              // 216
#define NM       (NROI * G3)                       // 27648 grid points

// Scratch (device globals: no allocation allowed)
__device__ int   d_v2p[2][CELLS];               // 22.5 MB
__device__ float d_pooled[2][NM][NB_C];         // 14.2 MB

// ---------------------------------------------------------------------------
// Kernel 1: init v2p = -1 (int4 vectorized) and zero the output scalar
// ---------------------------------------------------------------------------
__global__ void init_kernel(float* out) {
    const int4 neg1 = make_int4(-1, -1, -1, -1);
    int4* p = reinterpret_cast<int4*>(d_v2p);
    long n4 = (2L * CELLS) / 4;  // 1,408,000 — divisible by 4
    long i = (long)blockIdx.x * blockDim.x + threadIdx.x;
    for (; i < n4; i += (long)gridDim.x * blockDim.x)
        p[i] = neg1;
    if (blockIdx.x == 0 && threadIdx.x == 0) out[0] = 0.0f;
}

// ---------------------------------------------------------------------------
// Kernel 2: scatter voxel index into v2p, last-write(=max index)-wins
// ---------------------------------------------------------------------------
__global__ void scatter_kernel(const int* __restrict__ cd, const int* __restrict__ cs) {
    int i = blockIdx.x * blockDim.x + threadIdx.x;
    if (i >= 2 * NB_NTOT) return;
    int br = (i >= NB_NTOT);
    int v  = i - br * NB_NTOT;
    const int* coords = br ? cs : cd;
    int4 c = reinterpret_cast<const int4*>(coords)[v];   // (b, z, y, x)
    int flat = ((c.x * NB_DZ + c.y) * NB_DY + c.z) * NB_DX + c.w;
    atomicMax(&d_v2p[br][flat], v);
}

// ---------------------------------------------------------------------------
// Kernel 3: one warp per (grid point, branch). Lanes 0..26 probe the 27
// neighbor cells; valid hits within radius are accumulated coalesced
// (channels lane, lane+32 per lane) and the pooled mean row is written.
// ---------------------------------------------------------------------------
__global__ void pool_kernel(const float* __restrict__ gt,
                            const int*   __restrict__ cd, const float* __restrict__ fd,
                            const int*   __restrict__ cs, const float* __restrict__ fs) {
    int gwarp = (blockIdx.x * blockDim.x + threadIdx.x) >> 5;
    int lane  = threadIdx.x & 31;
    if (gwarp >= 2 * NM) return;
    int br = (gwarp >= NM);
    int m  = gwarp - br * NM;

    const int*   coords = br ? cs : cd;
    const float* feats  = br ? fs : fd;

    int roi  = m / G3;
    int cell = m - roi * G3;
    int ia = cell / 36;
    int ib = (cell / 6) % 6;
    int ic = cell % 6;

    // box: (cx, cy, cz, sx, sy, sz, heading, label)
    const float* box = gt + roi * 8;
    float bx = box[0], by = box[1], bz = box[2];
    float sx = box[3], sy = box[4], sz = box[5];
    float h  = box[6];

    // local grid point, rotate by heading, translate
    float lx = ((float)ia + 0.5f) / 6.0f * sx - sx * 0.5f;
    float ly = ((float)ib + 0.5f) / 6.0f * sy - sy * 0.5f;
    float lz = ((float)ic + 0.5f) / 6.0f * sz - sz * 0.5f;
    float ch = cosf(h), sh = sinf(h);
    float px = lx * ch - ly * sh + bx;
    float py = lx * sh + ly * ch + by;
    float pz = lz + bz;

    // downsampled voxel coordinate: floor(floor((p-pcr)/vox)/4)  (two-step, as ref)
    int gx = (int)floorf(floorf((px - 0.0f)  / 0.05f) * 0.25f);
    int gy = (int)floorf(floorf((py + 40.0f) / 0.05f) * 0.25f);
    int gz = (int)floorf(floorf((pz + 3.0f)  / 0.1f)  * 0.25f);
    int batch = roi / NB_NGT;

    int  pidx = -1;
    bool ok   = false;
    if (lane < 27) {
        int oz = lane / 9 - 1;
        int oy = (lane / 3) % 3 - 1;
        int ox = lane % 3 - 1;
        int z = gz + oz, y = gy + oy, x = gx + ox;
        if (z >= 0 && z < NB_DZ && y >= 0 && y < NB_DY && x >= 0 && x < NB_DX) {
            pidx = d_v2p[br][((batch * NB_DZ + z) * NB_DY + y) * NB_DX + x];
            if (pidx >= 0) {
                int4 cc = reinterpret_cast<const int4*>(coords)[pidx];  // (b,z,y,x)
                float vx = ((float)cc.w + 0.5f) * 0.2f + 0.0f;
                float vy = ((float)cc.z + 0.5f) * 0.2f - 40.0f;
                float vz = ((float)cc.y + 0.5f) * 0.4f - 3.0f;
                float dx = vx - px, dy = vy - py, dz = vz - pz;
                float d2 = dx * dx + dy * dy + dz * dz;
                ok = d2 < 0.16f;   // RADIUS^2 (nearest f32)
            }
        }
    }

    unsigned mask = __ballot_sync(0xffffffffu, ok);
    int cnt = __popc(mask);
    float w = 1.0f / fmaxf((float)cnt, 1.0f);

    float a0 = 0.0f, a1 = 0.0f;
    while (mask) {
        int src = __ffs(mask) - 1;
        mask &= (mask - 1);
        int p = __shfl_sync(0xffffffffu, pidx, src);
        const float* fr = feats + (long)p * NB_C;
        a0 += fr[lane];
        a1 += fr[lane + 32];
    }
    d_pooled[br][m][lane]      = a0 * w;
    d_pooled[br][m][lane + 32] = a1 * w;
}

// ---------------------------------------------------------------------------
// Kernel 4: per-ROI gfeat (mean over 216), normalize both branches,
// dot, abs, accumulate mean into out[0].
// ---------------------------------------------------------------------------
__global__ void final_kernel(float* out) {
    int roi = blockIdx.x;      // 128 blocks
    int c   = threadIdx.x;     // 64 threads

    float s0 = 0.0f, s1 = 0.0f;
    int base = roi * G3;
    for (int mm = 0; mm < G3; mm++) {
        s0 += d_pooled[0][base + mm][c];
        s1 += d_pooled[1][base + mm][c];
    }
    s0 *= (1.0f / (float)G3);
    s1 *= (1.0f / (float)G3);

    float n0 = s0 * s0, n1 = s1 * s1, dt = s0 * s1;
    // warp reduce (2 warps of 32)
    for (int o = 16; o > 0; o >>= 1) {
        n0 += __shfl_down_sync(0xffffffffu, n0, o);
        n1 += __shfl_down_sync(0xffffffffu, n1, o);
        dt += __shfl_down_sync(0xffffffffu, dt, o);
    }
    __shared__ float sh[3][2];
    if ((c & 31) == 0) {
        sh[0][c >> 5] = n0;
        sh[1][c >> 5] = n1;
        sh[2][c >> 5] = dt;
    }
    __syncthreads();
    if (c == 0) {
        float N0 = sh[0][0] + sh[0][1];
        float N1 = sh[1][0] + sh[1][1];
        float D  = sh[2][0] + sh[2][1];
        float norm0 = fmaxf(sqrtf(N0), 1e-12f);
        float norm1 = fmaxf(sqrtf(N1), 1e-12f);
        float dot = D / (norm0 * norm1);
        atomicAdd(out, fabsf(dot) * (1.0f / (float)NROI));
    }
}

// ---------------------------------------------------------------------------
extern "C" void kernel_launch(void* const* d_in, const int* in_sizes, int n_in,
                              void* d_out, int out_size) {
    const float* gt_boxes = (const float*)d_in[0];  // (2,64,8)
    const int*   cd       = (const int*)  d_in[1];  // (200000,4)
    const float* fd       = (const float*)d_in[2];  // (200000,64)
    const int*   cs       = (const int*)  d_in[3];
    const float* fs       = (const float*)d_in[4];
    float* out = (float*)d_out;

    // 1) init v2p + zero output: 1,408,000 int4 stores
    {
        int threads = 256;
        int blocks = (int)(((2L * CELLS) / 4 + threads - 1) / threads);  // 5500
        init_kernel<<<blocks, threads>>>(out);
    }
    // 2) scatter (400k atomics)
    {
        int threads = 256;
        int blocks = (2 * NB_NTOT + threads - 1) / threads;
        scatter_kernel<<<blocks, threads>>>(cd, cs);
    }
    // 3) pool: 55296 warps
    {
        int threads = 256;  // 8 warps per block
        int warps = 2 * NM;
        int blocks = (warps * 32 + threads - 1) / threads;  // 6912
        pool_kernel<<<blocks, threads>>>(gt_boxes, cd, fd, cs, fs);
    }
    // 4) reduce + dot + mean
    final_kernel<<<NROI, NB_C>>>(out);
}

// round 11
// speedup vs baseline: 1.1843x; 1.1843x over previous
#include <cuda_runtime.h>

// Problem constants (from reference)
#define NB_B     2
#define NB_NGT   64
#define NB_G     6
#define NB_C     64
#define NB_NVOX  100000
#define NB_NTOT  (NB_B * NB_NVOX)      // 200000 voxels per branch
#define NB_DZ    10
#define NB_DY    400
#define NB_DX    352
#define CELLS    (NB_B * NB_DZ * NB_DY * NB_DX)   // 2,816,000
#define NROI     (NB_B * NB_NGT)                   // 128
#define G3       (NB_G * NB_G * NB_G)              // 216
#define NM       (NROI * G3)                       // 27648 grid points

// Scratch (device globals — zero-initialized at module load).
// v2p encoding: 0 = empty, k>0 means voxel index k-1. atomicMax(v+1) keeps
// the LARGEST voxel index per cell == "last write wins" of the reference.
__device__ int   d_v2p[2][CELLS];                 // 22.5 MB (stays zero outside launch)
__device__ float d_gfeat[2][NROI][NB_C];          // 64 KB accumulators

// ---------------------------------------------------------------------------
// Kernel 1: zero the per-ROI accumulators + the output scalar (tiny)
// ---------------------------------------------------------------------------
__global__ void zero_kernel(float* out) {
    int i = blockIdx.x * blockDim.x + threadIdx.x;
    if (i < 2 * NROI * NB_C)
        reinterpret_cast<float*>(d_gfeat)[i] = 0.0f;
    if (i == 0) out[0] = 0.0f;
}

// ---------------------------------------------------------------------------
// Kernel 2: scatter voxel index (+1) into v2p, last-write(=max)-wins
// ---------------------------------------------------------------------------
__global__ void scatter_kernel(const int* __restrict__ cd, const int* __restrict__ cs) {
    int i = blockIdx.x * blockDim.x + threadIdx.x;
    if (i >= 2 * NB_NTOT) return;
    int br = (i >= NB_NTOT);
    int v  = i - br * NB_NTOT;
    const int* coords = br ? cs : cd;
    int4 c = reinterpret_cast<const int4*>(coords)[v];   // (b, z, y, x)
    int flat = ((c.x * NB_DZ + c.y) * NB_DY + c.z) * NB_DX + c.w;
    atomicMax(&d_v2p[br][flat], v + 1);
}

// ---------------------------------------------------------------------------
// Kernel 3: one warp per (grid point, branch). Lanes 0..26 probe the 27
// neighbor cells; valid in-radius hits are accumulated coalesced. The 8
// warps of a block all belong to the same ROI (216 % 8 == 0): block-level
// shared reduction, then ONE global atomicAdd per channel per block.
// ---------------------------------------------------------------------------
__global__ void pool_kernel(const float* __restrict__ gt,
                            const int*   __restrict__ cd, const float* __restrict__ fd,
                            const int*   __restrict__ cs, const float* __restrict__ fs) {
    __shared__ float smacc[8][NB_C];

    int wid   = threadIdx.x >> 5;
    int lane  = threadIdx.x & 31;
    int gwarp = blockIdx.x * 8 + wid;          // grid sized exactly: gwarp < 2*NM
    int br = (gwarp >= NM);
    int m  = gwarp - br * NM;

    const int*   coords = br ? cs : cd;
    const float* feats  = br ? fs : fd;

    int roi  = m / G3;
    int cell = m - roi * G3;
    int ia = cell / 36;
    int ib = (cell / 6) % 6;
    int ic = cell % 6;

    // box: (cx, cy, cz, sx, sy, sz, heading, label)
    const float* box = gt + roi * 8;
    float bx = box[0], by = box[1], bz = box[2];
    float sx = box[3], sy = box[4], sz = box[5];
    float h  = box[6];

    // local grid point, rotate by heading, translate
    float lx = ((float)ia + 0.5f) / 6.0f * sx - sx * 0.5f;
    float ly = ((float)ib + 0.5f) / 6.0f * sy - sy * 0.5f;
    float lz = ((float)ic + 0.5f) / 6.0f * sz - sz * 0.5f;
    float ch = cosf(h), sh = sinf(h);
    float px = lx * ch - ly * sh + bx;
    float py = lx * sh + ly * ch + by;
    float pz = lz + bz;

    // downsampled voxel coordinate: floor(floor((p-pcr)/vox)/4)  (two-step, as ref)
    int gx = (int)floorf(floorf((px - 0.0f)  / 0.05f) * 0.25f);
    int gy = (int)floorf(floorf((py + 40.0f) / 0.05f) * 0.25f);
    int gz = (int)floorf(floorf((pz + 3.0f)  / 0.1f)  * 0.25f);
    int batch = roi / NB_NGT;

    int  pidx = -1;
    bool ok   = false;
    if (lane < 27) {
        int oz = lane / 9 - 1;
        int oy = (lane / 3) % 3 - 1;
        int ox = lane % 3 - 1;
        int z = gz + oz, y = gy + oy, x = gx + ox;
        if (z >= 0 && z < NB_DZ && y >= 0 && y < NB_DY && x >= 0 && x < NB_DX) {
            int t = d_v2p[br][((batch * NB_DZ + z) * NB_DY + y) * NB_DX + x];
            if (t > 0) {
                pidx = t - 1;
                int4 cc = reinterpret_cast<const int4*>(coords)[pidx];  // (b,z,y,x)
                float vx = ((float)cc.w + 0.5f) * 0.2f + 0.0f;
                float vy = ((float)cc.z + 0.5f) * 0.2f - 40.0f;
                float vz = ((float)cc.y + 0.5f) * 0.4f - 3.0f;
                float dx = vx - px, dy = vy - py, dz = vz - pz;
                float d2 = dx * dx + dy * dy + dz * dz;
                ok = d2 < 0.16f;   // RADIUS^2 (nearest f32)
            }
        }
    }

    unsigned mask = __ballot_sync(0xffffffffu, ok);
    int cnt = __popc(mask);
    float w = 1.0f / fmaxf((float)cnt, 1.0f);

    float a0 = 0.0f, a1 = 0.0f;
    while (mask) {
        int src = __ffs(mask) - 1;
        mask &= (mask - 1);
        int p = __shfl_sync(0xffffffffu, pidx, src);
        const float* fr = feats + (long)p * NB_C;
        a0 += fr[lane];
        a1 += fr[lane + 32];
    }
    smacc[wid][lane]      = a0 * w;
    smacc[wid][lane + 32] = a1 * w;
    __syncthreads();

    // block-level reduction over 8 warps (all same roi/br), one atomic per ch
    int c = threadIdx.x;
    if (c < NB_C) {
        float s = 0.0f;
        #pragma unroll
        for (int ww = 0; ww < 8; ww++) s += smacc[ww][c];
        atomicAdd(&d_gfeat[br][roi][c], s);
    }
}

// ---------------------------------------------------------------------------
// Kernel 4: restore v2p to zero for the next graph replay (touched cells only)
// ---------------------------------------------------------------------------
__global__ void cleanup_kernel(const int* __restrict__ cd, const int* __restrict__ cs) {
    int i = blockIdx.x * blockDim.x + threadIdx.x;
    if (i >= 2 * NB_NTOT) return;
    int br = (i >= NB_NTOT);
    int v  = i - br * NB_NTOT;
    const int* coords = br ? cs : cd;
    int4 c = reinterpret_cast<const int4*>(coords)[v];
    int flat = ((c.x * NB_DZ + c.y) * NB_DY + c.z) * NB_DX + c.w;
    d_v2p[br][flat] = 0;
}

// ---------------------------------------------------------------------------
// Kernel 5: normalize both branches per ROI, dot, abs, mean into out[0]
// ---------------------------------------------------------------------------
__global__ void final_kernel(float* out) {
    int roi = blockIdx.x;      // 128 blocks
    int c   = threadIdx.x;     // 64 threads

    const float inv = 1.0f / (float)G3;
    float s0 = d_gfeat[0][roi][c] * inv;
    float s1 = d_gfeat[1][roi][c] * inv;

    float n0 = s0 * s0, n1 = s1 * s1, dt = s0 * s1;
    for (int o = 16; o > 0; o >>= 1) {
        n0 += __shfl_down_sync(0xffffffffu, n0, o);
        n1 += __shfl_down_sync(0xffffffffu, n1, o);
        dt += __shfl_down_sync(0xffffffffu, dt, o);
    }
    __shared__ float sh[3][2];
    if ((c & 31) == 0) {
        sh[0][c >> 5] = n0;
        sh[1][c >> 5] = n1;
        sh[2][c >> 5] = dt;
    }
    __syncthreads();
    if (c == 0) {
        float N0 = sh[0][0] + sh[0][1];
        float N1 = sh[1][0] + sh[1][1];
        float D  = sh[2][0] + sh[2][1];
        float norm0 = fmaxf(sqrtf(N0), 1e-12f);
        float norm1 = fmaxf(sqrtf(N1), 1e-12f);
        float dot = D / (norm0 * norm1);
        atomicAdd(out, fabsf(dot) * (1.0f / (float)NROI));
    }
}

// ---------------------------------------------------------------------------
extern "C" void kernel_launch(void* const* d_in, const int* in_sizes, int n_in,
                              void* d_out, int out_size) {
    const float* gt_boxes = (const float*)d_in[0];  // (2,64,8)
    const int*   cd       = (const int*)  d_in[1];  // (200000,4)
    const float* fd       = (const float*)d_in[2];  // (200000,64)
    const int*   cs       = (const int*)  d_in[3];
    const float* fs       = (const float*)d_in[4];
    float* out = (float*)d_out;

    // 1) zero accumulators + output (tiny)
    {
        int n = 2 * NROI * NB_C;
        zero_kernel<<<(n + 255) / 256, 256>>>(out);
    }
    // 2) scatter (400k atomics), v2p assumed all-zero (empty sentinel)
    {
        int threads = 256;
        int blocks = (2 * NB_NTOT + threads - 1) / threads;
        scatter_kernel<<<blocks, threads>>>(cd, cs);
    }
    // 3) pool + fused per-ROI accumulation: 55296 warps, 8 warps/block
    {
        int blocks = (2 * NM) / 8;   // 6912, exact
        pool_kernel<<<blocks, 256>>>(gt_boxes, cd, fd, cs, fs);
    }
    // 4) restore v2p to all-zero for next replay
    {
        int threads = 256;
        int blocks = (2 * NB_NTOT + threads - 1) / threads;
        cleanup_kernel<<<blocks, threads>>>(cd, cs);
    }
    // 5) normalize + dot + mean (tiny)
    final_kernel<<<NROI, NB_C>>>(out);
}